// round 16
// baseline (speedup 1.0000x reference)
#include <cuda_runtime.h>
#include <cuda_fp16.h>
#include <cstdint>
#include <cstddef>

#define NB   256
#define MM   512
#define DD   256

// ======================= scratch (device globals) ===========================
// Split-fp16 matrices stored as 16KB PANELS: panel(pr,pc) = rows pr*128..+127,
// K-cols pc*32..+31. Panel layout = exact smem image: row r at offset r*128,
// 8 x 16B groups (4 hi + 4 lo), group g stored at ((g ^ (r&7))<<4).
__device__ __align__(256) float  g_tr  [NB];
__device__ __align__(256) float  g_ssp [NB * 8];
__device__ __align__(256) __half g_xn  [NB * MM * 2 * DD];
__device__ __align__(256) __half g_xnT [NB * DD * 2 * MM];
__device__ __align__(256) __half g_Ba  [NB * DD * 2 * DD];
__device__ __align__(256) __half g_Bb  [NB * DD * 2 * DD];
__device__ __align__(256) __half g_Cm  [NB * DD * 2 * DD];
__device__ __align__(256) __half g_P0  [NB * DD * 2 * DD];
__device__ __align__(256) __half g_P1  [NB * DD * 2 * DD];

// ======================= PTX helpers ========================================
__device__ __forceinline__ uint32_t smem_u32(const void* p) {
    uint32_t a;
    asm("{ .reg .u64 t; cvta.to.shared.u64 t, %1; cvt.u32.u64 %0, t; }"
        : "=r"(a) : "l"(p));
    return a;
}

#define CP_BULK(dst_u32, src_gptr, bytes, mbar) \
    asm volatile("cp.async.bulk.shared::cluster.global.mbarrier::complete_tx::bytes " \
                 "[%0], [%1], %2, [%3];" \
                 :: "r"(dst_u32), "l"((const void*)(src_gptr)), \
                    "r"((uint32_t)(bytes)), "r"(mbar) : "memory")

#define MBARRIER_INIT(mbar, count) \
    asm volatile("mbarrier.init.shared.b64 [%0], %1;" \
                 :: "r"((uint32_t)(mbar)), "r"((uint32_t)(count)) : "memory")
#define MBARRIER_EXPECT_TX(mbar, tx) \
    asm volatile("mbarrier.arrive.expect_tx.shared.b64 _, [%0], %1;" \
                 :: "r"((uint32_t)(mbar)), "r"((uint32_t)(tx)) : "memory")
#define MBARRIER_WAIT_PARITY(mbar_addr, phase_parity) do {                    \
    uint32_t _mbar = (uint32_t)(mbar_addr);                                   \
    uint32_t _parity = (uint32_t)(phase_parity);                              \
    uint32_t _done;                                                           \
    asm volatile(                                                             \
        "{\n\t.reg .pred p;\n\t"                                              \
        "mbarrier.try_wait.parity.acquire.cta.shared::cta.b64 p, [%1], %2;\n\t" \
        "selp.b32 %0, 1, 0, p;\n\t}"                                          \
        : "=r"(_done) : "r"(_mbar), "r"(_parity) : "memory");                 \
    if (!_done) {                                                             \
        asm volatile(                                                         \
            "{\n\t.reg .pred P1;\n\t"                                         \
            "WAIT_LOOP_%=:\n\t"                                               \
            "mbarrier.try_wait.parity.acquire.cta.shared::cta.b64 P1, [%0], %1, 0x989680;\n\t" \
            "@P1 bra.uni WAIT_DONE_%=;\n\t"                                   \
            "bra.uni WAIT_LOOP_%=;\n\t"                                       \
            "WAIT_DONE_%=:\n\t}"                                              \
            :: "r"(_mbar), "r"(_parity) : "memory");                          \
    }                                                                         \
} while (0)

#define LDM_X4(r0, r1, r2, r3, addr) \
    asm volatile("ldmatrix.sync.aligned.m8n8.x4.shared.b16 {%0,%1,%2,%3}, [%4];" \
                 : "=r"(r0), "=r"(r1), "=r"(r2), "=r"(r3) : "r"(addr))

#define MMA_FP16(d, a0, a1, a2, a3, b0, b1) \
    asm("mma.sync.aligned.m16n8k16.row.col.f32.f16.f16.f32 " \
        "{%0,%1,%2,%3}, {%4,%5,%6,%7}, {%8,%9}, {%0,%1,%2,%3};" \
        : "+f"((d)[0]), "+f"((d)[1]), "+f"((d)[2]), "+f"((d)[3]) \
        : "r"(a0), "r"(a1), "r"(a2), "r"(a3), "r"(b0), "r"(b1))

__device__ __forceinline__ uint32_t h2_half(uint32_t x) {   // *0.5 packed fp16x2
    uint32_t d;
    asm("mul.rn.f16x2 %0, %1, %2;" : "=r"(d) : "r"(x), "r"(0x38003800u));
    return d;
}
__device__ __forceinline__ uint32_t h2_bits(__half2 h) {
    return *reinterpret_cast<uint32_t*>(&h);
}

// ==== fused: mean + center + panel writes + sumsq partials ==================
// grid (8, NB); block 256. Each block owns one 32-wide d-chunk of one batch.
// Dynamic smem: x-slab [32 d][513 m] floats (~66KB). One gmem read of x.
__global__ __launch_bounds__(256) void center_kernel(const float* __restrict__ x) {
    extern __shared__ float tile[];           // [32][513]
    __shared__ float pmu[32][9];
    __shared__ float mu_s[32];
    __shared__ float red[256];

    const int n  = blockIdx.y;
    const int dc = blockIdx.x * 32;
    const int tid = threadIdx.x;
    const int tx = tid & 31;                  // d within chunk
    const int tg = tid >> 5;                  // m group (64 rows each)

    char* xb  = (char*)(g_xn  + (size_t)n * MM * 2 * DD);
    char* xtb = (char*)(g_xnT + (size_t)n * DD * 2 * MM);
    const float* xs = x + (size_t)n * MM * DD;

    // pass 1: load slab (coalesced over d) + per-thread column partial sum
    float sx = 0.f;
    #pragma unroll 4
    for (int mm = 0; mm < 64; mm++) {
        int m = tg * 64 + mm;
        float v = xs[(size_t)m * DD + dc + tx];
        tile[tx * 513 + m] = v;
        sx += v;
    }
    pmu[tx][tg] = sx;
    __syncthreads();
    if (tid < 32) {
        float s = 0.f;
        #pragma unroll
        for (int gq = 0; gq < 8; gq++) s += pmu[tid][gq];
        mu_s[tid] = s * (1.f / (float)MM);
    }
    __syncthreads();

    const int d = dc + tx;
    const float mu = mu_s[tx];
    const uint32_t gh  = (uint32_t)((d >> 3) & 3);      // xn group for this d

    // pass 2: center, write xn hi panel + xnT split panels, accumulate ssq
    float ssq = 0.f;
    #pragma unroll 4
    for (int mm = 0; mm < 64; mm++) {
        int m = tg * 64 + mm;
        float v = tile[tx * 513 + m] - mu;
        ssq += v * v;
        __half hh = __float2half_rn(v);
        // xn (hi only; lo plane never read)
        size_t panx = ((size_t)(m >> 7) * 8 + (dc >> 5)) * 16384u;
        int rr = m & 127;
        uint32_t offx = (uint32_t)(rr * 128 + ((gh ^ (uint32_t)(rr & 7)) << 4) +
                                   (d & 7) * 2);
        *(__half*)(xb + panx + offx) = hh;
        // xnT (split hi/lo)
        __half hl = __float2half_rn(v - __half2float(hh));
        size_t pant = ((size_t)(d >> 7) * 16 + (m >> 5)) * 16384u;
        int rr2 = d & 127;
        uint32_t gt  = (uint32_t)((m >> 3) & 3);
        uint32_t ohi = (uint32_t)(rr2 * 128 + ((gt ^ (uint32_t)(rr2 & 7)) << 4) +
                                  (m & 7) * 2);
        uint32_t olo = (uint32_t)(rr2 * 128 + (((4 + gt) ^ (uint32_t)(rr2 & 7)) << 4) +
                                  (m & 7) * 2);
        *(__half*)(xtb + pant + ohi) = hh;
        *(__half*)(xtb + pant + olo) = hl;
    }
    red[tid] = ssq;
    __syncthreads();
    for (int s = 128; s > 0; s >>= 1) {
        if (tid < s) red[tid] += red[tid + s];
        __syncthreads();
    }
    if (tid == 0) g_ssp[n * 8 + blockIdx.x] = red[0];
}

__global__ __launch_bounds__(32) void reduce_tr_kernel() {
    int n = blockIdx.x, t = threadIdx.x;
    float v = (t < 8) ? g_ssp[n * 8 + t] : 0.f;
    #pragma unroll
    for (int s = 4; s > 0; s >>= 1)
        v += __shfl_down_sync(0xFFFFFFFFu, v, s);
    if (t == 0) g_tr[n] = v;
}

// ===================== fp16 mma.sync batched GEMM, bulk-copy panels =========
// 19 params: Cout,Amat,Bmat,Dmat,C2out,A2mat,Ktot,sA,sB,sC,sD,
//            mode,sym,sqr,npass,npassb,ofmt,wlo0,wlo1
// npass/npassb: 1 = AhBh ; 2 = +AhBl ; 3 = +AlBh   (job0 / job1)
#define STG_B      32768u
#define MBAR_OFF   98304u
#define SMEM_DYN   98432

__global__ __launch_bounds__(256, 2) void gemm_h(
    void* __restrict__ Cout, const __half* __restrict__ Amat,
    const __half* __restrict__ Bmat, const __half* __restrict__ Dmat,
    void* __restrict__ C2out, const __half* __restrict__ A2mat,
    int Ktot, long long sA, long long sB, long long sC, long long sD,
    int mode, int sym, int sqr, int npass, int npassb,
    int ofmt, int wlo0, int wlo1)
{
    extern __shared__ char smem[];
    const uint32_t sb  = smem_u32(smem);
    const uint32_t mb0 = sb + MBAR_OFF;

    const int tid  = threadIdx.x;
    const int wid  = tid >> 5, lane = tid & 31;
    const int wm   = wid & 1;
    const int wn   = wid >> 1;
    const int n    = blockIdx.z;

    int ti, tj, job = 0, mymode = mode;
    if (sym) {
        int tt = blockIdx.x;
        if (tt >= 3) { job = 1; tt -= 3; mymode = 0; }
        ti = (tt == 2) ? 1 : 0; tj = (tt != 0) ? 1 : 0;
    } else {
        ti = blockIdx.x; tj = blockIdx.y;
    }
    const int rb = ti * 128;
    const int cb = tj * 128;

    const int  mynp    = job ? npassb : npass;
    const bool do_diag = sqr && sym && (job == 0) && (ti == tj);
    const bool need_al = (mynp >= 3) && !do_diag;
    const bool need_bl = (mynp >= 2) || do_diag;
    const bool wlo     = job ? (wlo1 != 0) : (wlo0 != 0);
    const bool do_t    = sym && (rb != cb);

    const __half* An = (job ? A2mat : Amat) + (size_t)n * sA;
    const __half* Bn = Bmat + (size_t)n * sB;
    const char* DnB = Dmat ? (const char*)(Dmat + (size_t)n * sD) : nullptr;

    const int nch = Ktot >> 5;
    const size_t aprow = (size_t)ti * nch * 16384u;
    const size_t bprow = (size_t)tj * nch * 16384u;

    const bool dpref = (mymode == 1) && (DnB != nullptr) && !do_t;
    const uint32_t sD1 = (uint32_t)(nch % 3);
    const uint32_t sD2 = (uint32_t)((nch + 1) % 3);
    const size_t dpanbase = ((size_t)ti * 8 + (size_t)tj * 4) * 16384u;

    if (tid == 0) {
        MBARRIER_INIT(mb0,      1);
        MBARRIER_INIT(mb0 + 8,  1);
        MBARRIER_INIT(mb0 + 16, 1);
        MBARRIER_INIT(mb0 + 24, 1);
        MBARRIER_INIT(mb0 + 32, 1);
    }
    __syncthreads();

    if (tid == 0) {
        #pragma unroll
        for (int pc_ = 0; pc_ < 2; pc_++) {
            uint32_t mbar = mb0 + (uint32_t)pc_ * 8u;
            uint32_t dst  = sb + (uint32_t)pc_ * STG_B;
            const char* sa = (const char*)An + aprow + (size_t)pc_ * 16384u;
            const char* sp = (const char*)Bn + bprow + (size_t)pc_ * 16384u;
            if (do_diag) {
                MBARRIER_EXPECT_TX(mbar, 16384u);
                CP_BULK(dst, sa, 16384u, mbar);
            } else {
                MBARRIER_EXPECT_TX(mbar, 32768u);
                CP_BULK(dst, sa, 16384u, mbar);
                CP_BULK(dst + 16384u, sp, 16384u, mbar);
            }
        }
    }

    // ldmatrix lane geometry
    const int t  = lane >> 3, s7 = lane & 7;
    const int chA = t >> 1;
    const int rAl = wm * 64 + (t & 1) * 8 + s7;
    const int chB = t & 1;
    const int rBl = wn * 32 + (t >> 1) * 8 + s7;

    float acc[4][4][4];
    #pragma unroll
    for (int i = 0; i < 4; i++)
        #pragma unroll
        for (int j = 0; j < 4; j++)
            #pragma unroll
            for (int q = 0; q < 4; q++) acc[i][j][q] = 0.f;

    for (int c = 0; c < nch; c++) {
        const int s = c % 3;
        MBARRIER_WAIT_PARITY(mb0 + (uint32_t)s * 8u, (c / 3) & 1);
        __syncthreads();

        if (tid == 0) {
            if (c + 2 < nch) {
                const int c2 = c + 2, s2 = c2 % 3;
                uint32_t mbar = mb0 + (uint32_t)s2 * 8u;
                uint32_t dst  = sb + (uint32_t)s2 * STG_B;
                const char* sa = (const char*)An + aprow + (size_t)c2 * 16384u;
                const char* sp = (const char*)Bn + bprow + (size_t)c2 * 16384u;
                if (do_diag) {
                    MBARRIER_EXPECT_TX(mbar, 16384u);
                    CP_BULK(dst, sa, 16384u, mbar);
                } else {
                    MBARRIER_EXPECT_TX(mbar, 32768u);
                    CP_BULK(dst, sa, 16384u, mbar);
                    CP_BULK(dst + 16384u, sp, 16384u, mbar);
                }
            } else if (dpref && c == nch - 2) {
                uint32_t dst = sb + sD1 * STG_B;
                MBARRIER_EXPECT_TX(mb0 + 24, 32768u);
                CP_BULK(dst,           DnB + dpanbase,            16384u, mb0 + 24);
                CP_BULK(dst + 16384u,  DnB + dpanbase + 16384u,   16384u, mb0 + 24);
            } else if (dpref && c == nch - 1) {
                uint32_t dst = sb + sD2 * STG_B;
                MBARRIER_EXPECT_TX(mb0 + 32, 32768u);
                CP_BULK(dst,           DnB + dpanbase + 32768u,   16384u, mb0 + 32);
                CP_BULK(dst + 16384u,  DnB + dpanbase + 49152u,   16384u, mb0 + 32);
            }
        }

        const uint32_t aB = sb + (uint32_t)s * STG_B;
        const uint32_t bB = do_diag ? aB : (aB + 16384u);

        #pragma unroll
        for (int kk = 0; kk < 2; kk++) {
            uint32_t bh[2][4], bl[2][4], ah[4][4], al[4][4];
            const int ghA = (kk << 1) + chA;
            const int ghB = (kk << 1) + chB;
            #pragma unroll
            for (int p = 0; p < 2; p++) {
                uint32_t h_ = bB + (uint32_t)((rBl + p * 16) * 128 + (ghB ^ s7) * 16);
                LDM_X4(bh[p][0], bh[p][1], bh[p][2], bh[p][3], h_);
            }
            if (need_bl) {
                #pragma unroll
                for (int p = 0; p < 2; p++) {
                    uint32_t l_ = bB + (uint32_t)((rBl + p * 16) * 128 + ((4 + ghB) ^ s7) * 16);
                    LDM_X4(bl[p][0], bl[p][1], bl[p][2], bl[p][3], l_);
                }
            }
            #pragma unroll
            for (int mi = 0; mi < 4; mi++) {
                uint32_t h_ = aB + (uint32_t)((rAl + mi * 16) * 128 + (ghA ^ s7) * 16);
                LDM_X4(ah[mi][0], ah[mi][1], ah[mi][2], ah[mi][3], h_);
            }
            if (need_al) {
                #pragma unroll
                for (int mi = 0; mi < 4; mi++) {
                    uint32_t l_ = aB + (uint32_t)((rAl + mi * 16) * 128 + ((4 + ghA) ^ s7) * 16);
                    LDM_X4(al[mi][0], al[mi][1], al[mi][2], al[mi][3], l_);
                }
            }
            if (do_diag) {
                #pragma unroll
                for (int p = 0; p < 2; p++)
                    #pragma unroll
                    for (int q = 0; q < 4; q++) bh[p][q] = h2_half(bh[p][q]);
            }

            // pass 1: Ah x Bh
            #pragma unroll
            for (int mi = 0; mi < 4; mi++)
                #pragma unroll
                for (int p = 0; p < 2; p++)
                    #pragma unroll
                    for (int q = 0; q < 2; q++)
                        MMA_FP16(acc[mi][p*2+q], ah[mi][0], ah[mi][1], ah[mi][2],
                                 ah[mi][3], bh[p][2*q], bh[p][2*q+1]);
            // pass 2: Ah x Bl
            if (need_bl) {
                #pragma unroll
                for (int mi = 0; mi < 4; mi++)
                    #pragma unroll
                    for (int p = 0; p < 2; p++)
                        #pragma unroll
                        for (int q = 0; q < 2; q++)
                            MMA_FP16(acc[mi][p*2+q], ah[mi][0], ah[mi][1], ah[mi][2],
                                     ah[mi][3], bl[p][2*q], bl[p][2*q+1]);
            }
            // pass 3: Al x Bh
            if (need_al) {
                #pragma unroll
                for (int mi = 0; mi < 4; mi++)
                    #pragma unroll
                    for (int p = 0; p < 2; p++)
                        #pragma unroll
                        for (int q = 0; q < 2; q++)
                            MMA_FP16(acc[mi][p*2+q], al[mi][0], al[mi][1], al[mi][2],
                                     al[mi][3], bh[p][2*q], bh[p][2*q+1]);
            }
        }
    }
    __syncthreads();

    // ---------------- epilogue ----------------
    if (dpref) {
        MBARRIER_WAIT_PARITY(mb0 + 24, 0);
        MBARRIER_WAIT_PARITY(mb0 + 32, 0);
    }

    const int g = lane >> 2, tig = lane & 3;
    float* stg = reinterpret_cast<float*>(smem);

    if (do_diag) {      // C_raw = acc + acc^T
        #pragma unroll
        for (int mi = 0; mi < 4; mi++)
            #pragma unroll
            for (int nj = 0; nj < 4; nj++) {
                const int cl = wn * 32 + nj * 8 + 2 * tig;
                #pragma unroll
                for (int h = 0; h < 2; h++) {
                    const int rl = wm * 64 + mi * 16 + g + 8 * h;
                    stg[rl * 129 + cl]     = acc[mi][nj][2 * h];
                    stg[rl * 129 + cl + 1] = acc[mi][nj][2 * h + 1];
                }
            }
        __syncthreads();
        #pragma unroll
        for (int mi = 0; mi < 4; mi++)
            #pragma unroll
            for (int nj = 0; nj < 4; nj++) {
                const int cl = wn * 32 + nj * 8 + 2 * tig;
                #pragma unroll
                for (int h = 0; h < 2; h++) {
                    const int rl = wm * 64 + mi * 16 + g + 8 * h;
                    acc[mi][nj][2 * h]     += stg[cl * 129 + rl];
                    acc[mi][nj][2 * h + 1] += stg[(cl + 1) * 129 + rl];
                }
            }
    }

    float ts = 0.f;
    if (mymode >= 2) ts = g_tr[n];
    const float sc2 = (mymode == 2) ? (-0.5f / ts) : 0.f;
    const float sc3 = (mymode == 3) ? rsqrtf(ts / (float)(MM - 1)) : 0.f;

    char*  ChB = nullptr;
    float* Cf  = nullptr;
    if (ofmt == 0) ChB = (char*)((__half*)(job ? C2out : Cout) + (size_t)n * sC);
    else           Cf  = (float*)Cout + (size_t)n * sC;

    const size_t pidx = dpanbase + (size_t)wn * 16384u;
    const char* dsm = smem + (size_t)(wn < 2 ? sD1 : sD2) * STG_B +
                      (size_t)(wn & 1) * 16384u;
    if (do_t) __syncthreads();

    #pragma unroll
    for (int mi = 0; mi < 4; mi++) {
        #pragma unroll
        for (int nj = 0; nj < 4; nj++) {
            const int cl = wn * 32 + nj * 8 + 2 * tig;
            const int col = cb + cl;
            #pragma unroll
            for (int h = 0; h < 2; h++) {
                const int rl = wm * 64 + mi * 16 + g + 8 * h;
                const int row = rb + rl;
                float v0 = acc[mi][nj][2 * h];
                float v1 = acc[mi][nj][2 * h + 1];
                const uint32_t ohi = (uint32_t)(rl * 128 +
                                     ((nj ^ (rl & 7)) << 4) + tig * 4);
                const uint32_t olo = (uint32_t)(rl * 128 +
                                     (((4 + nj) ^ (rl & 7)) << 4) + tig * 4);
                if (mymode == 1) {
                    float2 dh, dl;
                    if (dpref) {
                        dh = __half22float2(*(const __half2*)(dsm + ohi));
                        dl = __half22float2(*(const __half2*)(dsm + olo));
                    } else {
                        dh = __half22float2(*(const __half2*)(DnB + pidx + ohi));
                        dl = __half22float2(*(const __half2*)(DnB + pidx + olo));
                    }
                    v0 -= 1.5f * (dh.x + dl.x);
                    v1 -= 1.5f * (dh.y + dl.y);
                    if (row == col)     v0 += 1.5f;
                    if (row == col + 1) v1 += 1.5f;
                } else if (mymode == 2) {
                    v0 *= sc2; v1 *= sc2;
                    if (row == col)     v0 += 1.5f;
                    if (row == col + 1) v1 += 1.5f;
                } else if (mymode == 3) {
                    v0 *= sc3; v1 *= sc3;
                }
                if (ofmt == 0) {
                    __half2 hh = __float22half2_rn(make_float2(v0, v1));
                    *(__half2*)(ChB + pidx + ohi) = hh;
                    if (wlo) {
                        float2 f = __half22float2(hh);
                        *(__half2*)(ChB + pidx + olo) =
                            __float22half2_rn(make_float2(v0 - f.x, v1 - f.y));
                    }
                } else {
                    *(float2*)(Cf + (size_t)row * DD + col) = make_float2(v0, v1);
                }
                if (do_t) {
                    stg[rl * 129 + cl]     = v0;
                    stg[rl * 129 + cl + 1] = v1;
                }
            }
        }
    }

    // mirrored tile: C[cb..][rb..] = (this tile)^T, panel-format 16B stores
    if (do_t) {
        __syncthreads();
        const int r2    = tid >> 1;
        const int cbase = (tid & 1) * 64;
        #pragma unroll
        for (int q = 0; q < 8; q++) {
            const int c0 = cbase + q * 8;
            float w[8];
            #pragma unroll
            for (int u = 0; u < 8; u++) w[u] = stg[(c0 + u) * 129 + r2];
            __half2 h0 = __float22half2_rn(make_float2(w[0], w[1]));
            __half2 h1 = __float22half2_rn(make_float2(w[2], w[3]));
            __half2 h2 = __float22half2_rn(make_float2(w[4], w[5]));
            __half2 h3 = __float22half2_rn(make_float2(w[6], w[7]));
            const size_t p2 = ((size_t)tj * 8 + (size_t)ti * 4 + (size_t)(c0 >> 5))
                              * 16384u;
            const uint32_t gh2 = (uint32_t)((c0 >> 3) & 3);
            const uint32_t oh2 = (uint32_t)(r2 * 128 + ((gh2 ^ (r2 & 7)) << 4));
            *(uint4*)(ChB + p2 + oh2) =
                make_uint4(h2_bits(h0), h2_bits(h1), h2_bits(h2), h2_bits(h3));
            if (wlo) {
                float2 f0 = __half22float2(h0), f1 = __half22float2(h1);
                float2 f2 = __half22float2(h2), f3 = __half22float2(h3);
                __half2 l0 = __float22half2_rn(make_float2(w[0]-f0.x, w[1]-f0.y));
                __half2 l1 = __float22half2_rn(make_float2(w[2]-f1.x, w[3]-f1.y));
                __half2 l2 = __float22half2_rn(make_float2(w[4]-f2.x, w[5]-f2.y));
                __half2 l3 = __float22half2_rn(make_float2(w[6]-f3.x, w[7]-f3.y));
                const uint32_t ol2 = (uint32_t)(r2 * 128 +
                                     (((4 + gh2) ^ (r2 & 7)) << 4));
                *(uint4*)(ChB + p2 + ol2) =
                    make_uint4(h2_bits(l0), h2_bits(l1), h2_bits(l2), h2_bits(l3));
            }
        }
    }
}

// ======================= host launcher ======================================
extern "C" void kernel_launch(void* const* d_in, const int* in_sizes, int n_in,
                              void* d_out, int out_size) {
    const float* x = (const float*)d_in[0];
    float* out = (float*)d_out;

    __half *xn, *xnT, *Ba, *Bb, *Cm, *P0, *P1;
    cudaGetSymbolAddress((void**)&xn,  g_xn);
    cudaGetSymbolAddress((void**)&xnT, g_xnT);
    cudaGetSymbolAddress((void**)&Ba,  g_Ba);
    cudaGetSymbolAddress((void**)&Bb,  g_Bb);
    cudaGetSymbolAddress((void**)&Cm,  g_Cm);
    cudaGetSymbolAddress((void**)&P0,  g_P0);
    cudaGetSymbolAddress((void**)&P1,  g_P1);

    cudaFuncSetAttribute(gemm_h,
                         cudaFuncAttributeMaxDynamicSharedMemorySize, SMEM_DYN);
    const int CENTER_SMEM = 32 * 513 * 4;     // 65664
    cudaFuncSetAttribute(center_kernel,
                         cudaFuncAttributeMaxDynamicSharedMemorySize, CENTER_SMEM);

    const long long sM  = (long long)DD * 2 * DD;
    const long long sXT = (long long)DD * 2 * MM;
    const long long sXN = (long long)MM * 2 * DD;
    const long long sO  = (long long)MM * DD;
    const dim3 gSym(3, 1, NB);
    const dim3 gSym2(6, 1, NB);

    center_kernel<<<dim3(DD / 32, NB), 256, CENTER_SMEM>>>(x);
    reduce_tr_kernel<<<NB, 32>>>();

    // args (19): C, A, B, D, C2, A2, K, sA, sB, sC, sD,
    //            mode, sym, sqr, npass, npassb, ofmt, wlo0, wlo1

    // sigma -> Ba = B0   [K=512, sym, squaring, 3-pass]
    gemm_h<<<gSym, 256, SMEM_DYN>>>(Ba, xnT, xnT, nullptr, nullptr, nullptr,
                                    MM, sXT, sXT, sM, 0,
                                    2, 1, 1, 3, 3, 0, 1, 1);
    // iter 1: Cm = B0^2 (squaring, 3-pass)
    gemm_h<<<gSym, 256, SMEM_DYN>>>(Cm, Ba, Ba, nullptr, nullptr, nullptr,
                                    DD, sM, sM, sM, 0,
                                    0, 1, 1, 3, 3, 0, 1, 1);
    //         Bb = Cm*B0 - 1.5Cm + 1.5I  (B1)  [D prefetch, 3-pass]
    gemm_h<<<gSym, 256, SMEM_DYN>>>(Bb, Cm, Ba, Cm, nullptr, nullptr,
                                    DD, sM, sM, sM, sM,
                                    1, 1, 0, 3, 3, 0, 1, 1);
    // iter 2: {Cm = B1^2 (squaring) , P0 = B0*B1 (P2, 2-pass, lo dead)}
    gemm_h<<<gSym2, 256, SMEM_DYN>>>(Cm, Bb, Bb, nullptr, P0, Ba,
                                     DD, sM, sM, sM, 0,
                                     0, 1, 1, 3, 2, 0, 1, 0);
    //         Ba = Cm*B1 - 1.5Cm + 1.5I  (B2)  [D prefetch, 3-pass]
    gemm_h<<<gSym, 256, SMEM_DYN>>>(Ba, Cm, Bb, Cm, nullptr, nullptr,
                                    DD, sM, sM, sM, sM,
                                    1, 1, 0, 3, 3, 0, 1, 1);
    // iter 3: {Cm = B2^2 (squaring) , P1 = P2*B2 (P3, 2-pass, lo dead)}
    gemm_h<<<gSym2, 256, SMEM_DYN>>>(Cm, Ba, Ba, nullptr, P1, P0,
                                     DD, sM, sM, sM, 0,
                                     0, 1, 1, 3, 2, 0, 1, 0);
    //         Bb = Cm*B2 - 1.5Cm + 1.5I  (B3)  [D prefetch, 3-pass]
    gemm_h<<<gSym, 256, SMEM_DYN>>>(Bb, Cm, Ba, Cm, nullptr, nullptr,
                                    DD, sM, sM, sM, sM,
                                    1, 1, 0, 3, 3, 0, 1, 1);
    // iter 4: P0 = P3*B3 (P4) — 2-pass, P4-lo dead (final is 1-pass)
    gemm_h<<<gSym, 256, SMEM_DYN>>>(P0, P1, Bb, nullptr, nullptr, nullptr,
                                    DD, sM, sM, sM, 0,
                                    0, 1, 0, 2, 2, 0, 0, 1);
    // final: out = xn*P4*rsqrt(sumsq/(M-1)) — 1-pass (AhBh), fp32 out
    gemm_h<<<dim3(4, 2, NB), 256, SMEM_DYN>>>(out, xn, P0, nullptr, nullptr,
                                              nullptr, DD, sXN, sM, sO, 0,
                                              3, 0, 0, 1, 1, 1, 1, 1);
}

// round 17
// speedup vs baseline: 1.0329x; 1.0329x over previous
#include <cuda_runtime.h>
#include <cuda_fp16.h>
#include <cstdint>
#include <cstddef>

#define NB   256
#define MM   512
#define DD   256

// ======================= scratch (device globals) ===========================
// Split-fp16 matrices stored as 16KB PANELS: panel(pr,pc) = rows pr*128..+127,
// K-cols pc*32..+31. Panel layout = exact smem image: row r at offset r*128,
// 8 x 16B groups (4 hi + 4 lo), group g stored at ((g ^ (r&7))<<4).
__device__ __align__(256) float  g_tr  [NB];
__device__ __align__(256) float  g_ssp [NB * 8];
__device__ __align__(256) __half g_xn  [NB * MM * 2 * DD];
__device__ __align__(256) __half g_xnT [NB * DD * 2 * MM];
__device__ __align__(256) __half g_Ba  [NB * DD * 2 * DD];
__device__ __align__(256) __half g_Bb  [NB * DD * 2 * DD];
__device__ __align__(256) __half g_Cm  [NB * DD * 2 * DD];
__device__ __align__(256) __half g_P0  [NB * DD * 2 * DD];
__device__ __align__(256) __half g_P1  [NB * DD * 2 * DD];

// ======================= PTX helpers ========================================
__device__ __forceinline__ uint32_t smem_u32(const void* p) {
    uint32_t a;
    asm("{ .reg .u64 t; cvta.to.shared.u64 t, %1; cvt.u32.u64 %0, t; }"
        : "=r"(a) : "l"(p));
    return a;
}

#define CP_BULK(dst_u32, src_gptr, bytes, mbar) \
    asm volatile("cp.async.bulk.shared::cluster.global.mbarrier::complete_tx::bytes " \
                 "[%0], [%1], %2, [%3];" \
                 :: "r"(dst_u32), "l"((const void*)(src_gptr)), \
                    "r"((uint32_t)(bytes)), "r"(mbar) : "memory")

#define MBARRIER_INIT(mbar, count) \
    asm volatile("mbarrier.init.shared.b64 [%0], %1;" \
                 :: "r"((uint32_t)(mbar)), "r"((uint32_t)(count)) : "memory")
#define MBARRIER_EXPECT_TX(mbar, tx) \
    asm volatile("mbarrier.arrive.expect_tx.shared.b64 _, [%0], %1;" \
                 :: "r"((uint32_t)(mbar)), "r"((uint32_t)(tx)) : "memory")
#define MBARRIER_WAIT_PARITY(mbar_addr, phase_parity) do {                    \
    uint32_t _mbar = (uint32_t)(mbar_addr);                                   \
    uint32_t _parity = (uint32_t)(phase_parity);                              \
    uint32_t _done;                                                           \
    asm volatile(                                                             \
        "{\n\t.reg .pred p;\n\t"                                              \
        "mbarrier.try_wait.parity.acquire.cta.shared::cta.b64 p, [%1], %2;\n\t" \
        "selp.b32 %0, 1, 0, p;\n\t}"                                          \
        : "=r"(_done) : "r"(_mbar), "r"(_parity) : "memory");                 \
    if (!_done) {                                                             \
        asm volatile(                                                         \
            "{\n\t.reg .pred P1;\n\t"                                         \
            "WAIT_LOOP_%=:\n\t"                                               \
            "mbarrier.try_wait.parity.acquire.cta.shared::cta.b64 P1, [%0], %1, 0x989680;\n\t" \
            "@P1 bra.uni WAIT_DONE_%=;\n\t"                                   \
            "bra.uni WAIT_LOOP_%=;\n\t"                                       \
            "WAIT_DONE_%=:\n\t}"                                              \
            :: "r"(_mbar), "r"(_parity) : "memory");                          \
    }                                                                         \
} while (0)

#define LDM_X4(r0, r1, r2, r3, addr) \
    asm volatile("ldmatrix.sync.aligned.m8n8.x4.shared.b16 {%0,%1,%2,%3}, [%4];" \
                 : "=r"(r0), "=r"(r1), "=r"(r2), "=r"(r3) : "r"(addr))

#define MMA_FP16(d, a0, a1, a2, a3, b0, b1) \
    asm("mma.sync.aligned.m16n8k16.row.col.f32.f16.f16.f32 " \
        "{%0,%1,%2,%3}, {%4,%5,%6,%7}, {%8,%9}, {%0,%1,%2,%3};" \
        : "+f"((d)[0]), "+f"((d)[1]), "+f"((d)[2]), "+f"((d)[3]) \
        : "r"(a0), "r"(a1), "r"(a2), "r"(a3), "r"(b0), "r"(b1))

__device__ __forceinline__ uint32_t h2_half(uint32_t x) {   // *0.5 packed fp16x2
    uint32_t d;
    asm("mul.rn.f16x2 %0, %1, %2;" : "=r"(d) : "r"(x), "r"(0x38003800u));
    return d;
}
__device__ __forceinline__ uint32_t h2_bits(__half2 h) {
    return *reinterpret_cast<uint32_t*>(&h);
}

// ==== fused mean+center, NO smem slab: pass1 streams x, pass2 re-reads ======
// (second read is L2-resident). grid (8, NB), block 256.
__global__ __launch_bounds__(256) void center_kernel(const float* __restrict__ x) {
    __shared__ float pmu[32][9];
    __shared__ float mu_s[32];
    __shared__ float red[256];

    const int n  = blockIdx.y;
    const int dc = blockIdx.x * 32;
    const int tid = threadIdx.x;
    const int tx = tid & 31;                  // d within chunk
    const int tg = tid >> 5;                  // m group (64 rows each)

    char* xb  = (char*)(g_xn  + (size_t)n * MM * 2 * DD);
    char* xtb = (char*)(g_xnT + (size_t)n * DD * 2 * MM);
    const float* xs = x + (size_t)n * MM * DD + dc + tx;

    // pass 1: column partial sums (coalesced 128B per warp-read)
    float sx = 0.f;
    #pragma unroll 8
    for (int mm = 0; mm < 64; mm++)
        sx += xs[(size_t)(tg * 64 + mm) * DD];
    pmu[tx][tg] = sx;
    __syncthreads();
    if (tid < 32) {
        float s = 0.f;
        #pragma unroll
        for (int gq = 0; gq < 8; gq++) s += pmu[tid][gq];
        mu_s[tid] = s * (1.f / (float)MM);
    }
    __syncthreads();

    const int d = dc + tx;
    const float mu = mu_s[tx];
    const uint32_t gh = (uint32_t)((d >> 3) & 3);

    // pass 2: re-read (L2-hot), center, write panels, accumulate ssq
    float ssq = 0.f;
    #pragma unroll 4
    for (int mm = 0; mm < 64; mm++) {
        int m = tg * 64 + mm;
        float v = xs[(size_t)m * DD] - mu;
        ssq += v * v;
        __half hh = __float2half_rn(v);
        // xn (hi only; lo plane never read)
        size_t panx = ((size_t)(m >> 7) * 8 + (dc >> 5)) * 16384u;
        int rr = m & 127;
        uint32_t offx = (uint32_t)(rr * 128 + ((gh ^ (uint32_t)(rr & 7)) << 4) +
                                   (d & 7) * 2);
        *(__half*)(xb + panx + offx) = hh;
        // xnT (split hi/lo)
        __half hl = __float2half_rn(v - __half2float(hh));
        size_t pant = ((size_t)(d >> 7) * 16 + (m >> 5)) * 16384u;
        int rr2 = d & 127;
        uint32_t gt  = (uint32_t)((m >> 3) & 3);
        uint32_t ohi = (uint32_t)(rr2 * 128 + ((gt ^ (uint32_t)(rr2 & 7)) << 4) +
                                  (m & 7) * 2);
        uint32_t olo = (uint32_t)(rr2 * 128 + (((4 + gt) ^ (uint32_t)(rr2 & 7)) << 4) +
                                  (m & 7) * 2);
        *(__half*)(xtb + pant + ohi) = hh;
        *(__half*)(xtb + pant + olo) = hl;
    }
    red[tid] = ssq;
    __syncthreads();
    for (int s = 128; s > 0; s >>= 1) {
        if (tid < s) red[tid] += red[tid + s];
        __syncthreads();
    }
    if (tid == 0) g_ssp[n * 8 + blockIdx.x] = red[0];
}

__global__ __launch_bounds__(32) void reduce_tr_kernel() {
    int n = blockIdx.x, t = threadIdx.x;
    float v = (t < 8) ? g_ssp[n * 8 + t] : 0.f;
    #pragma unroll
    for (int s = 4; s > 0; s >>= 1)
        v += __shfl_down_sync(0xFFFFFFFFu, v, s);
    if (t == 0) g_tr[n] = v;
}

// ===================== fp16 mma.sync batched GEMM, bulk-copy panels =========
// 19 params: Cout,Amat,Bmat,Dmat,C2out,A2mat,Ktot,sA,sB,sC,sD,
//            mode,sym,sqr,npass,npassb,ofmt,wlo0,wlo1
#define STG_B      32768u
#define MBAR_OFF   98304u
#define SMEM_DYN   98432

__global__ __launch_bounds__(256, 2) void gemm_h(
    void* __restrict__ Cout, const __half* __restrict__ Amat,
    const __half* __restrict__ Bmat, const __half* __restrict__ Dmat,
    void* __restrict__ C2out, const __half* __restrict__ A2mat,
    int Ktot, long long sA, long long sB, long long sC, long long sD,
    int mode, int sym, int sqr, int npass, int npassb,
    int ofmt, int wlo0, int wlo1)
{
    extern __shared__ char smem[];
    const uint32_t sb  = smem_u32(smem);
    const uint32_t mb0 = sb + MBAR_OFF;

    const int tid  = threadIdx.x;
    const int wid  = tid >> 5, lane = tid & 31;
    const int wm   = wid & 1;
    const int wn   = wid >> 1;
    const int n    = blockIdx.z;

    int ti, tj, job = 0, mymode = mode;
    if (sym) {
        int tt = blockIdx.x;
        if (tt >= 3) { job = 1; tt -= 3; mymode = 0; }
        ti = (tt == 2) ? 1 : 0; tj = (tt != 0) ? 1 : 0;
    } else {
        ti = blockIdx.x; tj = blockIdx.y;
    }
    const int rb = ti * 128;
    const int cb = tj * 128;

    const int  mynp    = job ? npassb : npass;
    const bool do_diag = sqr && sym && (job == 0) && (ti == tj);
    const bool need_al = (mynp >= 3) && !do_diag;
    const bool need_bl = (mynp >= 2) || do_diag;
    const bool wlo     = job ? (wlo1 != 0) : (wlo0 != 0);
    const bool do_t    = sym && (rb != cb);

    const __half* An = (job ? A2mat : Amat) + (size_t)n * sA;
    const __half* Bn = Bmat + (size_t)n * sB;
    const char* DnB = Dmat ? (const char*)(Dmat + (size_t)n * sD) : nullptr;

    const int nch = Ktot >> 5;
    const size_t aprow = (size_t)ti * nch * 16384u;
    const size_t bprow = (size_t)tj * nch * 16384u;

    const bool dpref = (mymode == 1) && (DnB != nullptr) && !do_t;
    const uint32_t sD1 = (uint32_t)(nch % 3);
    const uint32_t sD2 = (uint32_t)((nch + 1) % 3);
    const size_t dpanbase = ((size_t)ti * 8 + (size_t)tj * 4) * 16384u;

    if (tid == 0) {
        MBARRIER_INIT(mb0,      1);
        MBARRIER_INIT(mb0 + 8,  1);
        MBARRIER_INIT(mb0 + 16, 1);
        MBARRIER_INIT(mb0 + 24, 1);
        MBARRIER_INIT(mb0 + 32, 1);
    }
    __syncthreads();

    if (tid == 0) {
        #pragma unroll
        for (int pc_ = 0; pc_ < 2; pc_++) {
            uint32_t mbar = mb0 + (uint32_t)pc_ * 8u;
            uint32_t dst  = sb + (uint32_t)pc_ * STG_B;
            const char* sa = (const char*)An + aprow + (size_t)pc_ * 16384u;
            const char* sp = (const char*)Bn + bprow + (size_t)pc_ * 16384u;
            if (do_diag) {
                MBARRIER_EXPECT_TX(mbar, 16384u);
                CP_BULK(dst, sa, 16384u, mbar);
            } else {
                MBARRIER_EXPECT_TX(mbar, 32768u);
                CP_BULK(dst, sa, 16384u, mbar);
                CP_BULK(dst + 16384u, sp, 16384u, mbar);
            }
        }
    }

    // ldmatrix lane geometry
    const int t  = lane >> 3, s7 = lane & 7;
    const int chA = t >> 1;
    const int rAl = wm * 64 + (t & 1) * 8 + s7;
    const int chB = t & 1;
    const int rBl = wn * 32 + (t >> 1) * 8 + s7;

    float acc[4][4][4];
    #pragma unroll
    for (int i = 0; i < 4; i++)
        #pragma unroll
        for (int j = 0; j < 4; j++)
            #pragma unroll
            for (int q = 0; q < 4; q++) acc[i][j][q] = 0.f;

    for (int c = 0; c < nch; c++) {
        const int s = c % 3;
        MBARRIER_WAIT_PARITY(mb0 + (uint32_t)s * 8u, (c / 3) & 1);
        __syncthreads();

        if (tid == 0) {
            if (c + 2 < nch) {
                const int c2 = c + 2, s2 = c2 % 3;
                uint32_t mbar = mb0 + (uint32_t)s2 * 8u;
                uint32_t dst  = sb + (uint32_t)s2 * STG_B;
                const char* sa = (const char*)An + aprow + (size_t)c2 * 16384u;
                const char* sp = (const char*)Bn + bprow + (size_t)c2 * 16384u;
                if (do_diag) {
                    MBARRIER_EXPECT_TX(mbar, 16384u);
                    CP_BULK(dst, sa, 16384u, mbar);
                } else {
                    MBARRIER_EXPECT_TX(mbar, 32768u);
                    CP_BULK(dst, sa, 16384u, mbar);
                    CP_BULK(dst + 16384u, sp, 16384u, mbar);
                }
            } else if (dpref && c == nch - 2) {
                uint32_t dst = sb + sD1 * STG_B;
                MBARRIER_EXPECT_TX(mb0 + 24, 32768u);
                CP_BULK(dst,           DnB + dpanbase,            16384u, mb0 + 24);
                CP_BULK(dst + 16384u,  DnB + dpanbase + 16384u,   16384u, mb0 + 24);
            } else if (dpref && c == nch - 1) {
                uint32_t dst = sb + sD2 * STG_B;
                MBARRIER_EXPECT_TX(mb0 + 32, 32768u);
                CP_BULK(dst,           DnB + dpanbase + 32768u,   16384u, mb0 + 32);
                CP_BULK(dst + 16384u,  DnB + dpanbase + 49152u,   16384u, mb0 + 32);
            }
        }

        const uint32_t aB = sb + (uint32_t)s * STG_B;
        const uint32_t bB = do_diag ? aB : (aB + 16384u);

        #pragma unroll
        for (int kk = 0; kk < 2; kk++) {
            uint32_t bh[2][4], bl[2][4], ah[4][4], al[4][4];
            const int ghA = (kk << 1) + chA;
            const int ghB = (kk << 1) + chB;
            #pragma unroll
            for (int p = 0; p < 2; p++) {
                uint32_t h_ = bB + (uint32_t)((rBl + p * 16) * 128 + (ghB ^ s7) * 16);
                LDM_X4(bh[p][0], bh[p][1], bh[p][2], bh[p][3], h_);
            }
            if (need_bl) {
                #pragma unroll
                for (int p = 0; p < 2; p++) {
                    uint32_t l_ = bB + (uint32_t)((rBl + p * 16) * 128 + ((4 + ghB) ^ s7) * 16);
                    LDM_X4(bl[p][0], bl[p][1], bl[p][2], bl[p][3], l_);
                }
            }
            #pragma unroll
            for (int mi = 0; mi < 4; mi++) {
                uint32_t h_ = aB + (uint32_t)((rAl + mi * 16) * 128 + (ghA ^ s7) * 16);
                LDM_X4(ah[mi][0], ah[mi][1], ah[mi][2], ah[mi][3], h_);
            }
            if (need_al) {
                #pragma unroll
                for (int mi = 0; mi < 4; mi++) {
                    uint32_t l_ = aB + (uint32_t)((rAl + mi * 16) * 128 + ((4 + ghA) ^ s7) * 16);
                    LDM_X4(al[mi][0], al[mi][1], al[mi][2], al[mi][3], l_);
                }
            }
            if (do_diag) {
                #pragma unroll
                for (int p = 0; p < 2; p++)
                    #pragma unroll
                    for (int q = 0; q < 4; q++) bh[p][q] = h2_half(bh[p][q]);
            }

            // pass 1: Ah x Bh
            #pragma unroll
            for (int mi = 0; mi < 4; mi++)
                #pragma unroll
                for (int p = 0; p < 2; p++)
                    #pragma unroll
                    for (int q = 0; q < 2; q++)
                        MMA_FP16(acc[mi][p*2+q], ah[mi][0], ah[mi][1], ah[mi][2],
                                 ah[mi][3], bh[p][2*q], bh[p][2*q+1]);
            // pass 2: Ah x Bl
            if (need_bl) {
                #pragma unroll
                for (int mi = 0; mi < 4; mi++)
                    #pragma unroll
                    for (int p = 0; p < 2; p++)
                        #pragma unroll
                        for (int q = 0; q < 2; q++)
                            MMA_FP16(acc[mi][p*2+q], ah[mi][0], ah[mi][1], ah[mi][2],
                                     ah[mi][3], bl[p][2*q], bl[p][2*q+1]);
            }
            // pass 3: Al x Bh
            if (need_al) {
                #pragma unroll
                for (int mi = 0; mi < 4; mi++)
                    #pragma unroll
                    for (int p = 0; p < 2; p++)
                        #pragma unroll
                        for (int q = 0; q < 2; q++)
                            MMA_FP16(acc[mi][p*2+q], al[mi][0], al[mi][1], al[mi][2],
                                     al[mi][3], bh[p][2*q], bh[p][2*q+1]);
            }
        }
    }
    __syncthreads();

    // ---------------- epilogue ----------------
    if (dpref) {
        MBARRIER_WAIT_PARITY(mb0 + 24, 0);
        MBARRIER_WAIT_PARITY(mb0 + 32, 0);
    }

    const int g = lane >> 2, tig = lane & 3;
    float* stg = reinterpret_cast<float*>(smem);

    if (do_diag) {      // C_raw = acc + acc^T
        #pragma unroll
        for (int mi = 0; mi < 4; mi++)
            #pragma unroll
            for (int nj = 0; nj < 4; nj++) {
                const int cl = wn * 32 + nj * 8 + 2 * tig;
                #pragma unroll
                for (int h = 0; h < 2; h++) {
                    const int rl = wm * 64 + mi * 16 + g + 8 * h;
                    stg[rl * 129 + cl]     = acc[mi][nj][2 * h];
                    stg[rl * 129 + cl + 1] = acc[mi][nj][2 * h + 1];
                }
            }
        __syncthreads();
        #pragma unroll
        for (int mi = 0; mi < 4; mi++)
            #pragma unroll
            for (int nj = 0; nj < 4; nj++) {
                const int cl = wn * 32 + nj * 8 + 2 * tig;
                #pragma unroll
                for (int h = 0; h < 2; h++) {
                    const int rl = wm * 64 + mi * 16 + g + 8 * h;
                    acc[mi][nj][2 * h]     += stg[cl * 129 + rl];
                    acc[mi][nj][2 * h + 1] += stg[(cl + 1) * 129 + rl];
                }
            }
    }

    float ts = 0.f;
    if (mymode >= 2) ts = g_tr[n];
    const float sc2 = (mymode == 2) ? (-0.5f / ts) : 0.f;
    const float sc3 = (mymode == 3) ? rsqrtf(ts / (float)(MM - 1)) : 0.f;

    char*  ChB = nullptr;
    float* Cf  = nullptr;
    if (ofmt == 0) ChB = (char*)((__half*)(job ? C2out : Cout) + (size_t)n * sC);
    else           Cf  = (float*)Cout + (size_t)n * sC;

    const size_t pidx = dpanbase + (size_t)wn * 16384u;
    const char* dsm = smem + (size_t)(wn < 2 ? sD1 : sD2) * STG_B +
                      (size_t)(wn & 1) * 16384u;
    if (do_t) __syncthreads();

    #pragma unroll
    for (int mi = 0; mi < 4; mi++) {
        #pragma unroll
        for (int nj = 0; nj < 4; nj++) {
            const int cl = wn * 32 + nj * 8 + 2 * tig;
            const int col = cb + cl;
            #pragma unroll
            for (int h = 0; h < 2; h++) {
                const int rl = wm * 64 + mi * 16 + g + 8 * h;
                const int row = rb + rl;
                float v0 = acc[mi][nj][2 * h];
                float v1 = acc[mi][nj][2 * h + 1];
                const uint32_t ohi = (uint32_t)(rl * 128 +
                                     ((nj ^ (rl & 7)) << 4) + tig * 4);
                const uint32_t olo = (uint32_t)(rl * 128 +
                                     (((4 + nj) ^ (rl & 7)) << 4) + tig * 4);
                if (mymode == 1) {
                    float2 dh, dl;
                    if (dpref) {
                        dh = __half22float2(*(const __half2*)(dsm + ohi));
                        dl = __half22float2(*(const __half2*)(dsm + olo));
                    } else {
                        dh = __half22float2(*(const __half2*)(DnB + pidx + ohi));
                        dl = __half22float2(*(const __half2*)(DnB + pidx + olo));
                    }
                    v0 -= 1.5f * (dh.x + dl.x);
                    v1 -= 1.5f * (dh.y + dl.y);
                    if (row == col)     v0 += 1.5f;
                    if (row == col + 1) v1 += 1.5f;
                } else if (mymode == 2) {
                    v0 *= sc2; v1 *= sc2;
                    if (row == col)     v0 += 1.5f;
                    if (row == col + 1) v1 += 1.5f;
                } else if (mymode == 3) {
                    v0 *= sc3; v1 *= sc3;
                }
                if (ofmt == 0) {
                    __half2 hh = __float22half2_rn(make_float2(v0, v1));
                    *(__half2*)(ChB + pidx + ohi) = hh;
                    if (wlo) {
                        float2 f = __half22float2(hh);
                        *(__half2*)(ChB + pidx + olo) =
                            __float22half2_rn(make_float2(v0 - f.x, v1 - f.y));
                    }
                } else {
                    *(float2*)(Cf + (size_t)row * DD + col) = make_float2(v0, v1);
                }
                if (do_t) {
                    stg[rl * 129 + cl]     = v0;
                    stg[rl * 129 + cl + 1] = v1;
                }
            }
        }
    }

    // mirrored tile: C[cb..][rb..] = (this tile)^T, panel-format 16B stores
    if (do_t) {
        __syncthreads();
        const int r2    = tid >> 1;
        const int cbase = (tid & 1) * 64;
        #pragma unroll
        for (int q = 0; q < 8; q++) {
            const int c0 = cbase + q * 8;
            float w[8];
            #pragma unroll
            for (int u = 0; u < 8; u++) w[u] = stg[(c0 + u) * 129 + r2];
            __half2 h0 = __float22half2_rn(make_float2(w[0], w[1]));
            __half2 h1 = __float22half2_rn(make_float2(w[2], w[3]));
            __half2 h2 = __float22half2_rn(make_float2(w[4], w[5]));
            __half2 h3 = __float22half2_rn(make_float2(w[6], w[7]));
            const size_t p2 = ((size_t)tj * 8 + (size_t)ti * 4 + (size_t)(c0 >> 5))
                              * 16384u;
            const uint32_t gh2 = (uint32_t)((c0 >> 3) & 3);
            const uint32_t oh2 = (uint32_t)(r2 * 128 + ((gh2 ^ (r2 & 7)) << 4));
            *(uint4*)(ChB + p2 + oh2) =
                make_uint4(h2_bits(h0), h2_bits(h1), h2_bits(h2), h2_bits(h3));
            if (wlo) {
                float2 f0 = __half22float2(h0), f1 = __half22float2(h1);
                float2 f2 = __half22float2(h2), f3 = __half22float2(h3);
                __half2 l0 = __float22half2_rn(make_float2(w[0]-f0.x, w[1]-f0.y));
                __half2 l1 = __float22half2_rn(make_float2(w[2]-f1.x, w[3]-f1.y));
                __half2 l2 = __float22half2_rn(make_float2(w[4]-f2.x, w[5]-f2.y));
                __half2 l3 = __float22half2_rn(make_float2(w[6]-f3.x, w[7]-f3.y));
                const uint32_t ol2 = (uint32_t)(r2 * 128 +
                                     (((4 + gh2) ^ (r2 & 7)) << 4));
                *(uint4*)(ChB + p2 + ol2) =
                    make_uint4(h2_bits(l0), h2_bits(l1), h2_bits(l2), h2_bits(l3));
            }
        }
    }
}

// ======================= host launcher ======================================
extern "C" void kernel_launch(void* const* d_in, const int* in_sizes, int n_in,
                              void* d_out, int out_size) {
    const float* x = (const float*)d_in[0];
    float* out = (float*)d_out;

    __half *xn, *xnT, *Ba, *Bb, *Cm, *P0, *P1;
    cudaGetSymbolAddress((void**)&xn,  g_xn);
    cudaGetSymbolAddress((void**)&xnT, g_xnT);
    cudaGetSymbolAddress((void**)&Ba,  g_Ba);
    cudaGetSymbolAddress((void**)&Bb,  g_Bb);
    cudaGetSymbolAddress((void**)&Cm,  g_Cm);
    cudaGetSymbolAddress((void**)&P0,  g_P0);
    cudaGetSymbolAddress((void**)&P1,  g_P1);

    cudaFuncSetAttribute(gemm_h,
                         cudaFuncAttributeMaxDynamicSharedMemorySize, SMEM_DYN);

    const long long sM  = (long long)DD * 2 * DD;
    const long long sXT = (long long)DD * 2 * MM;
    const long long sXN = (long long)MM * 2 * DD;
    const long long sO  = (long long)MM * DD;
    const dim3 gSym(3, 1, NB);
    const dim3 gSym2(6, 1, NB);

    center_kernel<<<dim3(DD / 32, NB), 256>>>(x);
    reduce_tr_kernel<<<NB, 32>>>();

    // args (19): C, A, B, D, C2, A2, K, sA, sB, sC, sD,
    //            mode, sym, sqr, npass, npassb, ofmt, wlo0, wlo1

    // sigma -> Ba = B0   [K=512, sym, squaring, 3-pass]
    gemm_h<<<gSym, 256, SMEM_DYN>>>(Ba, xnT, xnT, nullptr, nullptr, nullptr,
                                    MM, sXT, sXT, sM, 0,
                                    2, 1, 1, 3, 3, 0, 1, 1);
    // iter 1: Cm = B0^2 (squaring, 3-pass)
    gemm_h<<<gSym, 256, SMEM_DYN>>>(Cm, Ba, Ba, nullptr, nullptr, nullptr,
                                    DD, sM, sM, sM, 0,
                                    0, 1, 1, 3, 3, 0, 1, 1);
    //         Bb = Cm*B0 - 1.5Cm + 1.5I  (B1)  [D prefetch, 3-pass]
    gemm_h<<<gSym, 256, SMEM_DYN>>>(Bb, Cm, Ba, Cm, nullptr, nullptr,
                                    DD, sM, sM, sM, sM,
                                    1, 1, 0, 3, 3, 0, 1, 1);
    // iter 2: {Cm = B1^2 (squaring) , P0 = B0*B1 (P2, 2-pass, lo dead)}
    gemm_h<<<gSym2, 256, SMEM_DYN>>>(Cm, Bb, Bb, nullptr, P0, Ba,
                                     DD, sM, sM, sM, 0,
                                     0, 1, 1, 3, 2, 0, 1, 0);
    //         Ba = Cm*B1 - 1.5Cm + 1.5I  (B2)  [D prefetch, 3-pass]
    gemm_h<<<gSym, 256, SMEM_DYN>>>(Ba, Cm, Bb, Cm, nullptr, nullptr,
                                    DD, sM, sM, sM, sM,
                                    1, 1, 0, 3, 3, 0, 1, 1);
    // iter 3: {Cm = B2^2 (squaring) , P1 = P2*B2 (P3, 2-pass, lo dead)}
    gemm_h<<<gSym2, 256, SMEM_DYN>>>(Cm, Ba, Ba, nullptr, P1, P0,
                                     DD, sM, sM, sM, 0,
                                     0, 1, 1, 3, 2, 0, 1, 0);
    //         Bb = Cm*B2 - 1.5Cm + 1.5I  (B3)  [D prefetch, 3-pass]
    gemm_h<<<gSym, 256, SMEM_DYN>>>(Bb, Cm, Ba, Cm, nullptr, nullptr,
                                    DD, sM, sM, sM, sM,
                                    1, 1, 0, 3, 3, 0, 1, 1);
    // iter 4: P0 = P3*B3 (P4) — 2-pass, P4-lo dead (final is 1-pass)
    gemm_h<<<gSym, 256, SMEM_DYN>>>(P0, P1, Bb, nullptr, nullptr, nullptr,
                                    DD, sM, sM, sM, 0,
                                    0, 1, 0, 2, 2, 0, 0, 1);
    // final: out = xn*P4*rsqrt(sumsq/(M-1)) — 1-pass (AhBh), fp32 out
    gemm_h<<<dim3(4, 2, NB), 256, SMEM_DYN>>>(out, xn, P0, nullptr, nullptr,
                                              nullptr, DD, sXN, sM, sO, 0,
                                              3, 0, 0, 1, 1, 1, 1, 1);
}